// round 3
// baseline (speedup 1.0000x reference)
#include <cuda_runtime.h>
#include <math.h>

// Problem constants
#define S_N   256
#define V_N   200
#define VH_N  100    // v per half
#define F_N   5
#define G_N   80
#define NT    16
#define NR    5
#define NROT  16
#define EPSF  1e-5f

#define TWO_PI_F 6.28318530717958647692f
#define DTH_F    0.39269908169872415481f
#define LOG2E_F  1.44269504088896340736f

// Scratch (static device arrays)
__device__ float d_PART[(size_t)2 * S_N * 32 * 256];    // [s*2+vh][j=0..31][rk]  16.8 MB
__device__ float d_GDN[(size_t)S_N * NROT * G_N * 8];   // [s][r][g][8]           10.5 MB
__device__ float d_PMAX[(size_t)2 * S_N * 400];         // [half][s][f*80+gp]      0.8 MB

// ---------------- packed f32x2 helpers ----------------
__device__ __forceinline__ unsigned long long ffma2(unsigned long long a,
                                                    unsigned long long b,
                                                    unsigned long long c) {
    unsigned long long d;
    asm("fma.rn.f32x2 %0, %1, %2, %3;" : "=l"(d) : "l"(a), "l"(b), "l"(c));
    return d;
}
__device__ __forceinline__ unsigned long long pack2(float x) {
    unsigned long long d;
    asm("mov.b64 %0, {%1, %1};" : "=l"(d) : "f"(x));
    return d;
}
__device__ __forceinline__ float2 unpack2(unsigned long long v) {
    float2 f;
    asm("mov.b64 {%0, %1}, %2;" : "=f"(f.x), "=f"(f.y) : "l"(v));
    return f;
}
__device__ __forceinline__ float ex2f(float x) {
    float r;
    asm("ex2.approx.f32 %0, %1;" : "=f"(r) : "f"(x));
    return r;
}

// ---------------------------------------------------------------------------
// k12a: grid (S_N, 2). Block = (s, v-half), 256 threads = (r,k).
// Stage A[100][32] in smem, accumulate the 32-wide partial GEMM row with
// packed FFMA2, theta-gaussian recomputed on the fly. Write raw partials.
// ---------------------------------------------------------------------------
__global__ __launch_bounds__(256) void k12a(const float* __restrict__ feat,
                                            const float* __restrict__ rho,
                                            const float* __restrict__ theta,
                                            const float* __restrict__ mask,
                                            const float* __restrict__ mu_rho,
                                            const float* __restrict__ sigma_rho,
                                            const float* __restrict__ mu_theta,
                                            const float* __restrict__ sigma_theta)
{
    __shared__ float As[VH_N * 32];   // 12.8 KB
    __shared__ float t_s[VH_N];

    int s   = blockIdx.x;
    int vh  = blockIdx.y;
    int tid = threadIdx.x;
    int r   = tid >> 4;
    int k   = tid & 15;

    // per-thread theta-gaussian constants:
    // tg = exp2(-((tr - wrap - mu_k) * sL)^2), sL = sqrt(log2e/(sig^2+eps))
    float mu_k = __ldg(&mu_theta[k]);            // all f rows identical
    float st   = __ldg(&sigma_theta[k]);
    float sL   = sqrtf(LOG2E_F / (st * st + EPSF));
    float rdel = (float)r * DTH_F;
    float c0   = -mu_k * sL;
    float c1   = -(TWO_PI_F + mu_k) * sL;

    // ---- stage A for this v-half ----
    if (tid < VH_N) {
        int v   = tid;
        int idx = s * V_N + vh * VH_N + v;
        float rh = rho[idx];
        float m  = mask[idx];
        t_s[v]   = theta[idx];
        float fv[5];
#pragma unroll
        for (int f = 0; f < 5; f++) fv[f] = feat[idx * 5 + f];
#pragma unroll
        for (int p = 0; p < NR; p++) {
            float mr = __ldg(&mu_rho[p * 16]);
            float sr = __ldg(&sigma_rho[p * 16]);
            float d  = rh - mr;
            float rg = ex2f(-(d * d) * (LOG2E_F / (sr * sr + EPSF)));
            float rm = rg * m;
            As[v * 32 + p * 6] = rm;
#pragma unroll
            for (int f = 0; f < 5; f++) As[v * 32 + p * 6 + 1 + f] = rm * fv[f];
        }
        As[v * 32 + 30] = 0.0f;
        As[v * 32 + 31] = 0.0f;
    }
    __syncthreads();

    // ---- main loop ----
    unsigned long long acc[16];
#pragma unroll
    for (int j = 0; j < 16; j++) acc[j] = 0ull;

    const float* pa = As;
#pragma unroll 4
    for (int v = 0; v < VH_N; v++, pa += 32) {
        float tr = t_s[v] + rdel;
        float c  = (tr >= TWO_PI_F) ? c1 : c0;
        float x  = fmaf(tr, sL, c);
        float tg = ex2f(-x * x);
        unsigned long long tg2 = pack2(tg);
        const ulonglong2* av = (const ulonglong2*)pa;
#pragma unroll
        for (int j = 0; j < 8; j++) {
            ulonglong2 q = av[j];
            acc[2 * j + 0] = ffma2(tg2, q.x, acc[2 * j + 0]);
            acc[2 * j + 1] = ffma2(tg2, q.y, acc[2 * j + 1]);
        }
    }

    // ---- write raw partials, coalesced [s2][j][rk] ----
    float a[32];
#pragma unroll
    for (int j = 0; j < 16; j++) {
        float2 f2 = unpack2(acc[j]);
        a[2 * j] = f2.x; a[2 * j + 1] = f2.y;
    }
    float* pp = d_PART + ((size_t)(s * 2 + vh)) * 32 * 256 + tid;
#pragma unroll
    for (int j = 0; j < 32; j++) pp[(size_t)j * 256] = a[j];
}

// ---------------------------------------------------------------------------
// k12b: combine halves, normalize, write GDN [s][r][g=p*16+k][8].
// ---------------------------------------------------------------------------
__global__ __launch_bounds__(256) void k12b()
{
    int s   = blockIdx.x;
    int tid = threadIdx.x;     // rk
    const float* p0 = d_PART + (size_t)(s * 2) * 8192 + tid;
    const float* p1 = p0 + 8192;

    float a[32];
#pragma unroll
    for (int j = 0; j < 32; j++)
        a[j] = p0[(size_t)j * 256] + p1[(size_t)j * 256];

    int r = tid >> 4, k = tid & 15;
    float* gbase = d_GDN + (((size_t)s * NROT + r) * G_N + k) * 8;
#pragma unroll
    for (int p = 0; p < NR; p++) {
        float inv = 1.0f / (a[p * 6] + EPSF);
        float4 o0 = make_float4(a[p * 6 + 1] * inv, a[p * 6 + 2] * inv,
                                a[p * 6 + 3] * inv, a[p * 6 + 4] * inv);
        float4 o1 = make_float4(a[p * 6 + 5] * inv, 0.0f, 0.0f, 0.0f);
        float4* po = (float4*)(gbase + (size_t)p * 128);
        po[0] = o0;
        po[1] = o1;
    }
}

// ---------------------------------------------------------------------------
// k3: grid (S_N, 2). Block = (s, rotation-half of 8), 320 threads =
// (rg 0..3, gp 0..79); each rg processes 2 rotations sharing each W load.
// Writes per-half max over rotations to d_PMAX.
// ---------------------------------------------------------------------------
__global__ __launch_bounds__(320) void k3_conv(const float* __restrict__ Wc)
{
    __shared__ float Wsh[G_N * G_N];    // 25.6 KB
    __shared__ float gsh[8 * G_N * 8];  // 20.5 KB (reused for reduction)

    int s    = blockIdx.x;
    int half = blockIdx.y;
    int tid  = threadIdx.x;
    int rg   = tid / 80;
    int gp   = tid % 80;

    for (int i = tid; i < G_N * G_N; i += 320) Wsh[i] = Wc[i];
    {
        const float4* src = (const float4*)(d_GDN + ((size_t)s * 16 + half * 8) * 640);
        float4* dst = (float4*)gsh;
        for (int i = tid; i < 1280; i += 320) dst[i] = src[i];
    }
    __syncthreads();

    const float* ga = &gsh[(rg * 2) * 640];
    const float* gb = ga + 640;
    float a0 = 0.f, a1 = 0.f, a2 = 0.f, a3 = 0.f, a4 = 0.f;
    float b0 = 0.f, b1 = 0.f, b2 = 0.f, b3 = 0.f, b4 = 0.f;
#pragma unroll 4
    for (int g = 0; g < G_N; g++) {
        float w   = Wsh[g * 80 + gp];
        float4 xa = *(const float4*)&ga[g * 8];
        float xa4 = ga[g * 8 + 4];
        float4 xb = *(const float4*)&gb[g * 8];
        float xb4 = gb[g * 8 + 4];
        a0 = fmaf(xa.x, w, a0); a1 = fmaf(xa.y, w, a1); a2 = fmaf(xa.z, w, a2);
        a3 = fmaf(xa.w, w, a3); a4 = fmaf(xa4,  w, a4);
        b0 = fmaf(xb.x, w, b0); b1 = fmaf(xb.y, w, b1); b2 = fmaf(xb.z, w, b2);
        b3 = fmaf(xb.w, w, b3); b4 = fmaf(xb4,  w, b4);
    }
    float m0 = fmaxf(a0, b0), m1 = fmaxf(a1, b1), m2 = fmaxf(a2, b2);
    float m3 = fmaxf(a3, b3), m4 = fmaxf(a4, b4);

    __syncthreads();
    float* red = gsh;                    // 4 * 400
    red[rg * 400 + 0 * 80 + gp] = m0;
    red[rg * 400 + 1 * 80 + gp] = m1;
    red[rg * 400 + 2 * 80 + gp] = m2;
    red[rg * 400 + 3 * 80 + gp] = m3;
    red[rg * 400 + 4 * 80 + gp] = m4;
    __syncthreads();

    float* pout = d_PMAX + (size_t)half * S_N * 400 + (size_t)s * 400;
    {
        int j = tid;
        float v = fmaxf(fmaxf(red[j], red[400 + j]), fmaxf(red[800 + j], red[1200 + j]));
        pout[j] = v;
        if (tid < 80) {
            int j2 = 320 + tid;
            float v2 = fmaxf(fmaxf(red[j2], red[400 + j2]),
                             fmaxf(red[800 + j2], red[1200 + j2]));
            pout[j2] = v2;
        }
    }
}

// ---------------------------------------------------------------------------
// k4: final max over halves + bias + relu, then fcc GEMV. grid S_N, 320 thr.
// ---------------------------------------------------------------------------
__global__ __launch_bounds__(320) void k4_fcc(const float* __restrict__ bc,
                                              const float* __restrict__ fw,
                                              const float* __restrict__ fb,
                                              float* __restrict__ out)
{
    __shared__ float drow[400];
    __shared__ float part[320];
    int s   = blockIdx.x;
    int tid = threadIdx.x;

    for (int j = tid; j < 400; j += 320) {
        float v = fmaxf(d_PMAX[(size_t)s * 400 + j],
                        d_PMAX[(size_t)S_N * 400 + (size_t)s * 400 + j]);
        drow[j] = fmaxf(v + bc[j], 0.0f);
    }
    __syncthreads();

    int c = tid / 80, g = tid % 80;
    const float* fwp = fw + (size_t)(c * 100) * 80 + g;
    float acc = 0.0f;
#pragma unroll 10
    for (int jj = 0; jj < 100; jj++)
        acc += drow[c * 100 + jj] * fwp[(size_t)jj * 80];
    part[tid] = acc;
    __syncthreads();

    if (tid < 80)
        out[(size_t)s * 80 + tid] = fb[tid] + part[tid] + part[80 + tid]
                                  + part[160 + tid] + part[240 + tid];
}

// ---------------------------------------------------------------------------
// k5: pairwise distances, score, data_loss. One block, 128 threads.
// out: [0:20480) global_desc, [20480] data_loss, [20481:20609) score
// ---------------------------------------------------------------------------
__global__ void k5_loss(float* __restrict__ out)
{
    int tid = threadIdx.x;
    const float* gd = out;
    int i = tid & 63;
    const float *xa, *xb;
    if (tid < 64) { xa = gd + (size_t)(64 + i) * 80;  xb = gd + (size_t)i * 80; }
    else          { xa = gd + (size_t)(128 + i) * 80; xb = gd + (size_t)(192 + i) * 80; }

    float d = 0.0f;
#pragma unroll 8
    for (int j = 0; j < 80; j++) {
        float df = xa[j] - xb[j];
        d += df * df;
    }
    out[20481 + tid] = d;

    __shared__ float sd[128];
    float rv = (tid < 64) ? fmaxf(d - 0.0f, 0.0f)
                          : fmaxf(10.0f - d, 0.0f);
    sd[tid] = rv;
    __syncthreads();

    if (tid == 0) {
        float mp = 0.0f, mn = 0.0f;
        for (int j = 0; j < 64; j++) { mp += sd[j]; mn += sd[64 + j]; }
        mp *= (1.0f / 64.0f); mn *= (1.0f / 64.0f);
        float vp = 0.0f, vn = 0.0f;
        for (int j = 0; j < 64; j++) {
            float a = sd[j]      - mp; vp += a * a;
            float c = sd[64 + j] - mn; vn += c * c;
        }
        out[20480] = sqrtf(vp / 63.0f) + sqrtf(vn / 63.0f) + mp + mn;
    }
}

// ---------------------------------------------------------------------------
extern "C" void kernel_launch(void* const* d_in, const int* in_sizes, int n_in,
                              void* d_out, int out_size)
{
    const float* input_feat  = (const float*)d_in[0];
    const float* rho_coords  = (const float*)d_in[1];
    const float* theta_coord = (const float*)d_in[2];
    const float* mask        = (const float*)d_in[3];
    const float* mu_rho      = (const float*)d_in[4];
    const float* sigma_rho   = (const float*)d_in[5];
    const float* mu_theta    = (const float*)d_in[6];
    const float* sigma_theta = (const float*)d_in[7];
    const float* W_conv      = (const float*)d_in[8];
    const float* b_conv      = (const float*)d_in[9];
    const float* fcc_w       = (const float*)d_in[10];
    const float* fcc_b       = (const float*)d_in[11];
    float* out = (float*)d_out;

    k12a<<<dim3(S_N, 2), 256>>>(input_feat, rho_coords, theta_coord, mask,
                                mu_rho, sigma_rho, mu_theta, sigma_theta);
    k12b<<<S_N, 256>>>();
    k3_conv<<<dim3(S_N, 2), 320>>>(W_conv);
    k4_fcc<<<S_N, 320>>>(b_conv, fcc_w, fcc_b, out);
    k5_loss<<<1, 128>>>(out);
}